// round 7
// baseline (speedup 1.0000x reference)
#include <cuda_runtime.h>

#define BB   256
#define TT   2048
#define INW  29
#define HH   64
#define GG   192   // 3*H
#define OUTW 11

// Scratch (no cudaMalloc allowed).
__device__ float g_gx[(size_t)2 * BB * TT * GG];       // [dir][b][t][g] (natural t)
__device__ float g_out0[(size_t)BB * TT * 2 * HH];      // [b][t][128]
__device__ float g_hT[2 * BB * HH];                     // [dir][b][h]

typedef unsigned long long u64;

__device__ __forceinline__ u64 pk2(float lo, float hi) {
    u64 r; asm("mov.b64 %0,{%1,%2};" : "=l"(r) : "f"(lo), "f"(hi)); return r;
}
__device__ __forceinline__ void upk2(u64 v, float& lo, float& hi) {
    asm("mov.b64 {%0,%1},%2;" : "=f"(lo), "=f"(hi) : "l"(v));
}
// Packed fp32x2 FMA (Blackwell FFMA2) — 2x FFMA throughput vs 3-reg FFMA.
__device__ __forceinline__ u64 fma2(u64 a, u64 b, u64 c) {
    u64 d; asm("fma.rn.f32x2 %0,%1,%2,%3;" : "=l"(d) : "l"(a), "l"(b), "l"(c)); return d;
}
__device__ __forceinline__ u64 add2(u64 a, u64 b) {
    u64 d; asm("add.rn.f32x2 %0,%1,%2;" : "=l"(d) : "l"(a), "l"(b)); return d;
}
__device__ __forceinline__ float hadd2(u64 v) {
    float lo, hi; upk2(v, lo, hi); return lo + hi;
}

__device__ __forceinline__ float sigm(float x)  { return __fdividef(1.f, 1.f + __expf(-x)); }
__device__ __forceinline__ float tanh_(float x) { return __fdividef(2.f, 1.f + __expf(-2.f * x)) - 1.f; }

// ---------------------------------------------------------------------------
// Layer-0 input GEMM. Bias folds in bhh for the r,z gates (j<128) so the
// recurrence only needs the n-gate hidden bias.
// ---------------------------------------------------------------------------
__global__ __launch_bounds__(192) void gx0_kernel(
    const float* __restrict__ x,
    const float* __restrict__ Wf, const float* __restrict__ bf,
    const float* __restrict__ Wb, const float* __restrict__ bb,
    const float* __restrict__ bhf, const float* __restrict__ bhb)
{
    int dir = blockIdx.z, b = blockIdx.y, t0 = blockIdx.x * 64;
    const float* W  = dir ? Wb : Wf;
    const float* bi = dir ? bb : bf;
    const float* bh = dir ? bhb : bhf;
    int j = threadIdx.x;

    u64 w2[INW];
#pragma unroll
    for (int k = 0; k < INW; k++) { float w = W[j * INW + k]; w2[k] = pk2(w, w); }
    float bias = bi[j] + ((j < 2 * HH) ? bh[j] : 0.f);

    __shared__ __align__(16) float2 xs[INW][32];   // [k][t-pair], 64 timesteps
    for (int idx = j; idx < 64 * INW; idx += 192) {
        int tt = idx / INW, k = idx - tt * INW;
        float v = x[((size_t)b * TT + t0 + tt) * INW + k];
        ((float*)&xs[k][tt >> 1])[tt & 1] = v;
    }
    __syncthreads();

    const ulonglong2* xsq = (const ulonglong2*)xs;  // [k][16] pairs-of-pairs
    float* gxp = g_gx + ((size_t)(dir * BB + b) * TT + t0) * GG + j;
#pragma unroll 1
    for (int p2 = 0; p2 < 16; p2++) {
        u64 a0 = 0ull, a1 = 0ull;
#pragma unroll
        for (int k = 0; k < INW; k++) {
            ulonglong2 v = xsq[k * 16 + p2];
            a0 = fma2(w2[k], v.x, a0);
            a1 = fma2(w2[k], v.y, a1);
        }
        float q0, q1, q2, q3;
        upk2(a0, q0, q1); upk2(a1, q2, q3);
        gxp[(size_t)(4 * p2)     * GG] = q0 + bias;
        gxp[(size_t)(4 * p2 + 1) * GG] = q1 + bias;
        gxp[(size_t)(4 * p2 + 2) * GG] = q2 + bias;
        gxp[(size_t)(4 * p2 + 3) * GG] = q3 + bias;
    }
}

// ---------------------------------------------------------------------------
// Layer-1 input GEMM (K=128), gate-triple layout, bhh folded for r,z gates.
// ---------------------------------------------------------------------------
__global__ __launch_bounds__(128, 2) void gx1_kernel(
    const float* __restrict__ Wf, const float* __restrict__ bf,
    const float* __restrict__ Wb, const float* __restrict__ bb,
    const float* __restrict__ bhf, const float* __restrict__ bhb)
{
    int dir = blockIdx.z, b = blockIdx.y, t0 = blockIdx.x * 64;
    const float* W  = dir ? Wb : Wf;
    const float* bi = dir ? bb : bf;
    const float* bh = dir ? bhb : bhf;
    int tid = threadIdx.x;
    int w = tid >> 5, l = tid & 31;
    int j  = (w << 4) | (l & 15);    // h-index 0..63
    int kh = l >> 4;                  // K-half

    u64 wr[32], wz[32], wn[32];
    {
        const u64* pr = (const u64*)(W + (size_t)(j)        * 128 + kh * 64);
        const u64* pz = (const u64*)(W + (size_t)(j + 64)   * 128 + kh * 64);
        const u64* pn = (const u64*)(W + (size_t)(j + 128)  * 128 + kh * 64);
#pragma unroll
        for (int i = 0; i < 32; i++) { wr[i] = pr[i]; wz[i] = pz[i]; wn[i] = pn[i]; }
    }
    float br = bi[j] + bh[j];
    float bz = bi[j + 64] + bh[j + 64];
    float bn = bi[j + 128];

    __shared__ __align__(16) float ins[64][128];   // [t][k], 32 KB
    {
        const float4* src = (const float4*)(g_out0 + ((size_t)b * TT + t0) * 128);
        float4* dst = (float4*)ins;
        for (int idx = tid; idx < 64 * 32; idx += 128) dst[idx] = src[idx];
    }
    __syncthreads();

    float* gxp = g_gx + ((size_t)(dir * BB + b) * TT + t0) * GG + j;
#pragma unroll 1
    for (int t = 0; t < 64; t++) {
        const ulonglong2* row = (const ulonglong2*)&ins[t][kh * 64];
        u64 ar0 = 0ull, ar1 = 0ull, az0 = 0ull, az1 = 0ull, an0 = 0ull, an1 = 0ull;
#pragma unroll
        for (int i = 0; i < 16; i++) {
            ulonglong2 v = row[i];
            ar0 = fma2(wr[2 * i],     v.x, ar0);
            ar1 = fma2(wr[2 * i + 1], v.y, ar1);
            az0 = fma2(wz[2 * i],     v.x, az0);
            az1 = fma2(wz[2 * i + 1], v.y, az1);
            an0 = fma2(wn[2 * i],     v.x, an0);
            an1 = fma2(wn[2 * i + 1], v.y, an1);
        }
        float sr = hadd2(add2(ar0, ar1));
        float sz = hadd2(add2(az0, az1));
        float sn = hadd2(add2(an0, an1));
        sr += __shfl_xor_sync(0xffffffffu, sr, 16);
        sz += __shfl_xor_sync(0xffffffffu, sz, 16);
        sn += __shfl_xor_sync(0xffffffffu, sn, 16);
        if (kh == 0) {
            gxp[(size_t)t * GG]       = sr + br;
            gxp[(size_t)t * GG + 64]  = sz + bz;
            gxp[(size_t)t * GG + 128] = sn + bn;
        }
    }
}

// ---------------------------------------------------------------------------
// GRU recurrence: ONE sequence per 128-thread CTA (512 CTAs, all resident).
// Thread = (h-index j, K-half kh) via lane halves (lanes l / l^16 pair up).
// 48 packed f32x2 weight regs per thread (96 regs total -> 4 CTAs/SM).
// Matvec over own K-half (48 fma2, chains of 8), one shfl_xor(16) per gate,
// epilogue computed redundantly in both K-halves (fully thread-local).
// kh0 writes h (double-buffered smem) + hT; kh1 writes g_out0.
// One __syncthreads per step. gx prefetched 1 step ahead (r,z biases
// pre-folded into gx; only bn remains).
// ---------------------------------------------------------------------------
__global__ __launch_bounds__(128, 4) void recur_kernel(
    const float* __restrict__ Whf, const float* __restrict__ bhf,
    const float* __restrict__ Whb, const float* __restrict__ bhb,
    int layer)
{
    int b   = blockIdx.x & (BB - 1);
    int dir = blockIdx.x >> 8;
    const float* W  = dir ? Whb : Whf;
    const float* bh = dir ? bhb : bhf;
    int tid = threadIdx.x;
    int w = tid >> 5, l = tid & 31;
    int j  = (w << 4) | (l & 15);    // h-index 0..63
    int kh = l >> 4;                  // K-half: h[kh*32 .. kh*32+31]

    u64 wr[16], wz[16], wn[16];
    {
        const u64* pr = (const u64*)(W + (size_t)(j)        * HH + kh * 32);
        const u64* pz = (const u64*)(W + (size_t)(j + 64)   * HH + kh * 32);
        const u64* pn = (const u64*)(W + (size_t)(j + 128)  * HH + kh * 32);
#pragma unroll
        for (int i = 0; i < 16; i++) { wr[i] = pr[i]; wz[i] = pz[i]; wn[i] = pn[i]; }
    }
    float bn = bh[j + 128];

    __shared__ __align__(16) float hbuf[2][HH];
    if (tid < HH) hbuf[0][tid] = 0.f;
    float hp = 0.f;

    long stp = dir ? -(long)GG : (long)GG;
    const float* gp = g_gx + ((size_t)(dir * BB + b) * TT + (dir ? TT - 1 : 0)) * GG + j;
    float fr0 = gp[0], fz0 = gp[64], fn0 = gp[128]; gp += stp;

    float* outp = 0;
    long ostp = 0;
    if (layer == 0) {
        int tout0 = dir ? (TT - 1) : 0;
        outp = g_out0 + ((size_t)b * TT + tout0) * (2 * HH) + dir * HH + j;
        ostp = dir ? -(long)(2 * HH) : (long)(2 * HH);
    }
    __syncthreads();

    for (int t = 0; t < TT; t++) {
        float fr1 = 0.f, fz1 = 0.f, fn1 = 0.f;
        if (t + 1 < TT) { fr1 = gp[0]; fz1 = gp[64]; fn1 = gp[128]; gp += stp; }

        const ulonglong2* hq = (const ulonglong2*)(hbuf[t & 1] + kh * 32);
        u64 ar0 = 0ull, ar1 = 0ull, az0 = 0ull, az1 = 0ull, an0 = 0ull, an1 = 0ull;
#pragma unroll
        for (int i = 0; i < 8; i++) {
            ulonglong2 v = hq[i];
            ar0 = fma2(wr[2 * i],     v.x, ar0);
            ar1 = fma2(wr[2 * i + 1], v.y, ar1);
            az0 = fma2(wz[2 * i],     v.x, az0);
            az1 = fma2(wz[2 * i + 1], v.y, az1);
            an0 = fma2(wn[2 * i],     v.x, an0);
            an1 = fma2(wn[2 * i + 1], v.y, an1);
        }
        float sr = hadd2(add2(ar0, ar1));
        float sz = hadd2(add2(az0, az1));
        float sn = hadd2(add2(an0, an1));
        sr += __shfl_xor_sync(0xffffffffu, sr, 16);
        sz += __shfl_xor_sync(0xffffffffu, sz, 16);
        sn += __shfl_xor_sync(0xffffffffu, sn, 16);

        float r = sigm(sr + fr0);
        float z = sigm(sz + fz0);
        float n = tanh_(fmaf(r, sn + bn, fn0));
        float hN = fmaf(z, hp - n, n);          // (1-z)n + z h
        hp = hN;
        if (kh == 0) hbuf[(t + 1) & 1][j] = hN;
        if (layer == 0 && kh == 1) *outp = hN;
        outp += ostp;

        __syncthreads();

        fr0 = fr1; fz0 = fz1; fn0 = fn1;
    }

    if (layer == 1 && kh == 0) g_hT[(dir * BB + b) * HH + j] = hp;
}

// ---------------------------------------------------------------------------
// Head: LayerNorm(concat(hTf, hTb)) -> ReLU(W1) -> W2. One block per batch.
// ---------------------------------------------------------------------------
__global__ __launch_bounds__(128) void head_kernel(
    const float* __restrict__ ln_g, const float* __restrict__ ln_b,
    const float* __restrict__ W1,  const float* __restrict__ b1,
    const float* __restrict__ W2,  const float* __restrict__ b2,
    float* __restrict__ out)
{
    int b = blockIdx.x, i = threadIdx.x;
    __shared__ float y[128];
    __shared__ float hh[64];
    __shared__ float red[16];

    float e = (i < 64) ? g_hT[(0 * BB + b) * HH + i]
                       : g_hT[(1 * BB + b) * HH + (i - 64)];
    float s = e, q = e * e;
#pragma unroll
    for (int o = 16; o > 0; o >>= 1) {
        s += __shfl_down_sync(0xffffffffu, s, o);
        q += __shfl_down_sync(0xffffffffu, q, o);
    }
    int w = i >> 5, lane = i & 31;
    if (lane == 0) { red[w] = s; red[8 + w] = q; }
    __syncthreads();
    float mu  = (red[0] + red[1] + red[2] + red[3]) * (1.f / 128.f);
    float ms  = (red[8] + red[9] + red[10] + red[11]) * (1.f / 128.f);
    float var = ms - mu * mu;
    float inv = rsqrtf(var + 1e-5f);
    y[i] = (e - mu) * inv * ln_g[i] + ln_b[i];
    __syncthreads();

    if (i < 64) {
        float a = b1[i];
#pragma unroll 4
        for (int k = 0; k < 128; k++) a = fmaf(W1[i * 128 + k], y[k], a);
        hh[i] = fmaxf(a, 0.f);
    }
    __syncthreads();
    if (i < OUTW) {
        float a = b2[i];
#pragma unroll
        for (int k = 0; k < 64; k++) a = fmaf(W2[i * 64 + k], hh[k], a);
        out[b * OUTW + i] = a;
    }
}

extern "C" void kernel_launch(void* const* d_in, const int* in_sizes, int n_in,
                              void* d_out, int out_size)
{
    const float* x     = (const float*)d_in[0];
    const float* Wih00 = (const float*)d_in[1];
    const float* Whh00 = (const float*)d_in[2];
    const float* bih00 = (const float*)d_in[3];
    const float* bhh00 = (const float*)d_in[4];
    const float* Wih01 = (const float*)d_in[5];
    const float* Whh01 = (const float*)d_in[6];
    const float* bih01 = (const float*)d_in[7];
    const float* bhh01 = (const float*)d_in[8];
    const float* Wih10 = (const float*)d_in[9];
    const float* Whh10 = (const float*)d_in[10];
    const float* bih10 = (const float*)d_in[11];
    const float* bhh10 = (const float*)d_in[12];
    const float* Wih11 = (const float*)d_in[13];
    const float* Whh11 = (const float*)d_in[14];
    const float* bih11 = (const float*)d_in[15];
    const float* bhh11 = (const float*)d_in[16];
    const float* ln_g  = (const float*)d_in[17];
    const float* ln_b  = (const float*)d_in[18];
    const float* W1    = (const float*)d_in[19];
    const float* b1    = (const float*)d_in[20];
    const float* W2    = (const float*)d_in[21];
    const float* b2    = (const float*)d_in[22];

    gx0_kernel<<<dim3(TT / 64, BB, 2), 192>>>(x, Wih00, bih00, Wih01, bih01, bhh00, bhh01);
    recur_kernel<<<512, 128>>>(Whh00, bhh00, Whh01, bhh01, 0);
    gx1_kernel<<<dim3(TT / 64, BB, 2), 128>>>(Wih10, bih10, Wih11, bih11, bhh10, bhh11);
    recur_kernel<<<512, 128>>>(Whh10, bhh10, Whh11, bhh11, 1);
    head_kernel<<<BB, 128>>>(ln_g, ln_b, W1, b1, W2, b2, (float*)d_out);
}